// round 13
// baseline (speedup 1.0000x reference)
#include <cuda_runtime.h>
#include <cuda_bf16.h>
#include <cuda_fp16.h>
#include <cstring>

// KAN layer: y[b,o] = sum_f lerp(coeff[f, i-1, o], coeff[f, i, o], t) + bias[o]
// B=4096, F=128, G=64, OUT=64.  i = clip(ceil((x+3)*10.5), 1, 63); t = (x+3)*10.5-(i-1)
//
// R12: two fixes from the R11 instruction census (phase-1 = half the issue
// budget; LDG.64 spans 2 lines -> within-LDG replay tax):
//  - split-line row layout: [128B c0 | 128B d]; 1 IADD3 -> LDG.32[o] +
//    LDG.32[o+128] (imm), each exactly ONE 128B line (cross-LDG 1.0 cyc/wf).
//  - phase-1 index math trimmed (~12 -> ~9 instrs/pair): F2I.RU, IMNMX x2,
//    FFMA pair, F2FP pack, IMAD offset.
//  - 4-feature HADD2 tree before fp16->fp32 cvt (halves cvt/accum cost).

#define F_DIM   128
#define G_SIZE  64
#define OUT_N   64
#define SPB     4
#define THREADS 256               // 8 warps = 4 samples x 2 feature-halves
#define B_TOTAL 4096
#define FH      64                // features per warp
#define ROW_BYTES 256

// [F][G] rows of 256B: bytes [0,128) = c0 half2 per lane, [128,256) = d half2
__device__ __align__(16) __half g_ilv[F_DIM * G_SIZE * OUT_N * 2];   // 2 MB

__global__ __launch_bounds__(256)
void kan_convert_kernel(const float* __restrict__ coeff)
{
    const int j  = blockIdx.x * 256 + threadIdx.x;   // 0..262143  (f,g,op)
    const int f  = j >> 11;
    const int g  = (j >> 5) & (G_SIZE - 1);
    const int op = j & 31;
    const int gn = min(g + 1, G_SIZE - 1);

    const float2 c0 = __ldg(reinterpret_cast<const float2*>(coeff + (f * G_SIZE + g ) * OUT_N) + op);
    const float2 c1 = __ldg(reinterpret_cast<const float2*>(coeff + (f * G_SIZE + gn) * OUT_N) + op);

    const __half2 h0 = __float22half2_rn(c0);
    const __half2 hd = __float22half2_rn(make_float2(c1.x - c0.x, c1.y - c0.y));

    char* row = reinterpret_cast<char*>(g_ilv) + (f * G_SIZE + g) * ROW_BYTES;
    *reinterpret_cast<__half2*>(row + op * 4)       = h0;   // c0 line
    *reinterpret_cast<__half2*>(row + 128 + op * 4) = hd;   // d line
}

__global__ __launch_bounds__(THREADS, 6)
void kan_main_kernel(const float* __restrict__ x,
                     const float* __restrict__ bias,
                     float* __restrict__ y)
{
    // sidx4[s*64+fp]: features {2fp,2fp+1} -> {off0, t0_h2, off1, t1_h2}
    __shared__ uint4  sidx4[SPB * F_DIM / 2];   // 4 KB
    __shared__ float2 part[SPB][32];            // 1 KB

    const int tid  = threadIdx.x;
    const int row0 = blockIdx.x * SPB;

    // ---- Phase 1: 2 consecutive features of one sample per thread ----
    {
        const int s  = tid >> 6;
        const int fp = tid & 63;
        const int f0 = fp << 1;
        const float2 xv = *reinterpret_cast<const float2*>(x + (row0 + s) * F_DIM + f0);

        uint4 e;
        {
            const float u  = fmaf(xv.x, 10.5f, 31.5f);     // (x+3)*10.5
            const float u1 = fmaf(xv.x, 10.5f, 32.5f);     // u + 1
            int i = __float2int_ru(u);                     // ceil
            i = min(max(i, 1), G_SIZE - 1);
            const float t = u1 - (float)i;                 // u - (i-1)
            const __half2 th = __float2half2_rn(t);
            memcpy(&e.y, &th, 4);
            e.x = (unsigned)(i * ROW_BYTES + (f0 * G_SIZE - 1) * ROW_BYTES);  // IMAD
        }
        {
            const float u  = fmaf(xv.y, 10.5f, 31.5f);
            const float u1 = fmaf(xv.y, 10.5f, 32.5f);
            int i = __float2int_ru(u);
            i = min(max(i, 1), G_SIZE - 1);
            const float t = u1 - (float)i;
            const __half2 th = __float2half2_rn(t);
            memcpy(&e.w, &th, 4);
            e.z = (unsigned)(i * ROW_BYTES + ((f0 + 1) * G_SIZE - 1) * ROW_BYTES);
        }
        sidx4[tid] = e;
    }
    __syncthreads();

    // ---- Phase 2: warp = (sample, feature-half); lane owns outputs {2l,2l+1} ----
    const int w    = tid >> 5;
    const int lane = tid & 31;
    const int s    = w >> 1;
    const int h    = w & 1;

    const uint4* sp = sidx4 + s * (F_DIM / 2) + h * (FH / 2);
    const char* base = reinterpret_cast<const char*>(g_ilv);
    const unsigned lane4 = lane * 4;

    float2 acc = make_float2(0.f, 0.f);

    #pragma unroll 8
    for (int q = 0; q < FH / 4; ++q) {             // 4 features per iteration
        const uint4 e0 = sp[2 * q];                // LDS.128 broadcast
        const uint4 e1 = sp[2 * q + 1];

        const unsigned o0 = e0.x + lane4;
        const unsigned o1 = e0.z + lane4;
        const unsigned o2 = e1.x + lane4;
        const unsigned o3 = e1.z + lane4;

        // each LDG.32 touches exactly one 128B line; +128 is an imm offset
        const __half2 c0a = *reinterpret_cast<const __half2*>(base + o0);
        const __half2 dda = *reinterpret_cast<const __half2*>(base + o0 + 128);
        const __half2 c0b = *reinterpret_cast<const __half2*>(base + o1);
        const __half2 ddb = *reinterpret_cast<const __half2*>(base + o1 + 128);
        const __half2 c0c = *reinterpret_cast<const __half2*>(base + o2);
        const __half2 ddc = *reinterpret_cast<const __half2*>(base + o2 + 128);
        const __half2 c0d = *reinterpret_cast<const __half2*>(base + o3);
        const __half2 ddd = *reinterpret_cast<const __half2*>(base + o3 + 128);

        __half2 t0, t1, t2, t3;
        memcpy(&t0, &e0.y, 4);
        memcpy(&t1, &e0.w, 4);
        memcpy(&t2, &e1.y, 4);
        memcpy(&t3, &e1.w, 4);

        const __half2 r0 = __hfma2(t0, dda, c0a);
        const __half2 r1 = __hfma2(t1, ddb, c0b);
        const __half2 r2 = __hfma2(t2, ddc, c0c);
        const __half2 r3 = __hfma2(t3, ddd, c0d);

        const __half2 rs = __hadd2(__hadd2(r0, r1), __hadd2(r2, r3));  // 4-way tree
        const float2  rf = __half22float2(rs);
        acc.x += rf.x;                              // fp32 accumulate
        acc.y += rf.y;
    }

    // ---- Phase 3: pair reduction + bias + store ----
    if (h == 1) part[s][lane] = acc;
    __syncthreads();
    if (h == 0) {
        const float2 pr = part[s][lane];
        const float2 bv = reinterpret_cast<const float2*>(bias)[lane];
        acc.x += pr.x + bv.x;
        acc.y += pr.y + bv.y;
        reinterpret_cast<float2*>(y + (row0 + s) * OUT_N)[lane] = acc;
    }
}

extern "C" void kernel_launch(void* const* d_in, const int* in_sizes, int n_in,
                              void* d_out, int out_size)
{
    const float* x     = (const float*)d_in[0];   // [4096, 128]
    const float* coeff = (const float*)d_in[1];   // [128, 64, 64]
    const float* bias  = (const float*)d_in[2];   // [64]
    float* y           = (float*)d_out;           // [4096, 64]

    kan_convert_kernel<<<F_DIM * G_SIZE * OUT_N / 2 / 256, 256>>>(coeff);
    kan_main_kernel<<<B_TOTAL / SPB, THREADS>>>(x, bias, y);
}